// round 15
// baseline (speedup 1.0000x reference)
#include <cuda_runtime.h>
#include <cuda_bf16.h>
#include <math.h>
#include <cstdint>

// Problem constants
#define B_    512
#define NS    128
#define IN_   2048
#define MEM_  64
#define OUT_  2048
#define RCOLS 65
#define KO    2176          // IN_ + 2*MEM_
#define NPAD  132

// ------------------------------------------------------------------
// Scratch (device globals)
// ------------------------------------------------------------------
__device__ float g_q  [B_ * MEM_];      // bias-init by pack, atomicAdd by proj
__device__ float g_xf [B_];
__device__ float g_xr [B_ * RCOLS];
__device__ float g_W  [IN_ * NPAD];
__device__ __nv_bfloat16 g_Ahi[B_ * KO];
__device__ __nv_bfloat16 g_Alo[B_ * KO];
__device__ __nv_bfloat16 g_Bhi[OUT_ * KO];
__device__ __nv_bfloat16 g_Blo[OUT_ * KO];
__device__ __nv_bfloat16 g_WBhi[80 * 64];
__device__ __nv_bfloat16 g_WBlo[80 * 64];

// ------------------------------------------------------------------
// Helpers
// ------------------------------------------------------------------
__device__ __forceinline__ uint32_t smem_u32(const void* p) {
    uint32_t a;
    asm("{ .reg .u64 t; cvta.to.shared.u64 t, %1; cvt.u32.u64 %0, t; }"
        : "=r"(a) : "l"(p));
    return a;
}
__device__ __forceinline__ void cp16(uint32_t dst, const void* src) {
    asm volatile("cp.async.cg.shared.global [%0], [%1], 16;" :: "r"(dst), "l"(src));
}
#define CP_COMMIT()  asm volatile("cp.async.commit_group;" ::: "memory")
#define CP_WAIT(n)   asm volatile("cp.async.wait_group %0;" :: "n"(n) : "memory")

__device__ __forceinline__ void ldm_x4(uint32_t* r, uint32_t addr) {
    asm volatile("ldmatrix.sync.aligned.m8n8.x4.shared.b16 {%0,%1,%2,%3}, [%4];"
        : "=r"(r[0]), "=r"(r[1]), "=r"(r[2]), "=r"(r[3]) : "r"(addr));
}
__device__ __forceinline__ void mma16816(float* c, const uint32_t* a, const uint32_t* b) {
    asm volatile(
        "mma.sync.aligned.m16n8k16.row.col.f32.bf16.bf16.f32 "
        "{%0,%1,%2,%3}, {%4,%5,%6,%7}, {%8,%9}, {%0,%1,%2,%3};"
        : "+f"(c[0]), "+f"(c[1]), "+f"(c[2]), "+f"(c[3])
        : "r"(a[0]), "r"(a[1]), "r"(a[2]), "r"(a[3]), "r"(b[0]), "r"(b[1]));
}
__device__ __forceinline__ void split_bf16(float v, __nv_bfloat16& h, __nv_bfloat16& l) {
    h = __float2bfloat16(v);
    l = __float2bfloat16(v - __bfloat162float(h));
}

// ==================================================================
// Prep: pack weights + bias-init the projection accumulators.
// ==================================================================
#define P_W    (IN_ * NPAD)
#define P_WB   (P_W + 80 * 64)
#define P_Q    (P_WB + B_ * MEM_)
#define P_XF   (P_Q + B_)
#define P_XR   (P_XF + B_ * RCOLS)
__global__ __launch_bounds__(256) void pack_kernel(
    const float* __restrict__ W_ar, const float* __restrict__ W_f,
    const float* __restrict__ W_r,
    const float* __restrict__ b_ar, const float* __restrict__ b_f,
    const float* __restrict__ b_r)
{
    int idx = blockIdx.x * 256 + threadIdx.x;
    if (idx >= P_XR) return;
    if (idx < P_W) {
        int k = idx / NPAD, c = idx - k * NPAD;
        float v = 0.f;
        if (c < 64)       v = W_ar[(size_t)k * 64 + c];
        else if (c == 64) v = W_f[k];
        else if (c < 130) v = W_r[(size_t)k * RCOLS + (c - 65)];
        g_W[idx] = v;
    } else if (idx < P_WB) {
        int e = idx - P_W;
        int j = e >> 6, k = e & 63;
        float v = 0.f;
        if (j < 65)       v = W_r[(size_t)(IN_ + k) * RCOLS + j];
        else if (j == 65) v = W_f[IN_ + k];
        __nv_bfloat16 h, l;
        split_bf16(v, h, l);
        int dst = j * 64 + (((k >> 3) ^ (j & 7)) << 3) + (k & 7);
        g_WBhi[dst] = h;
        g_WBlo[dst] = l;
    } else if (idx < P_Q) {
        int e = idx - P_WB;
        g_q[e] = b_ar[e & 63];
    } else if (idx < P_XF) {
        g_xf[idx - P_Q] = b_f[0];
    } else {
        int e = idx - P_XF;
        g_xr[e] = b_r[e % RCOLS];
    }
}

// W_o [K=2176][N=2048] -> g_B* [N][K] bf16 hi/lo (tiled transpose)
__global__ __launch_bounds__(256) void conv_B_kernel(const float* __restrict__ W_o)
{
    __shared__ float t[32][33];
    const int k0 = blockIdx.x * 32;
    const int n0 = blockIdx.y * 32;
    const int tid = threadIdx.x;
    #pragma unroll
    for (int p = 0; p < 4; p++) {
        int r = (tid >> 5) + p * 8, c = tid & 31;
        t[r][c] = W_o[(size_t)(k0 + r) * OUT_ + n0 + c];
    }
    __syncthreads();
    #pragma unroll
    for (int p = 0; p < 2; p++) {
        int r = (tid >> 4) + p * 16;
        int cc = (tid & 15) * 2;
        float v0 = t[cc][r], v1 = t[cc + 1][r];
        __nv_bfloat16 h0, l0, h1, l1;
        split_bf16(v0, h0, l0);
        split_bf16(v1, h1, l1);
        __nv_bfloat162 hp; hp.x = h0; hp.y = h1;
        __nv_bfloat162 lp; lp.x = l0; lp.y = l1;
        *(__nv_bfloat162*)(g_Bhi + (size_t)(n0 + r) * KO + k0 + cc) = hp;
        *(__nv_bfloat162*)(g_Blo + (size_t)(n0 + r) * KO + k0 + cc) = lp;
    }
}

// ==================================================================
// Kernel A: projections, GROUP=8 x 2 k-halves, atomic combine.
// ==================================================================
#define GROUP 8
#define KHALF (IN_ / 2)
#define CW4   33
#define KQ2   16
#define PTH   (CW4 * KQ2)
#define KSLC  (KHALF / KQ2)

__global__ __launch_bounds__(PTH) void proj_kernel(const float* __restrict__ x)
{
    extern __shared__ float psm[];
    float* xs  = psm;
    float* red = psm + GROUP * KHALF;
    const int b0 = blockIdx.x * GROUP;
    const int kh = blockIdx.y;
    const int kofs = kh * KHALF;

    for (int i = threadIdx.x; i < GROUP * (KHALF / 4); i += PTH) {
        int g = i >> 8, k4 = i & 255;
        ((float4*)(xs + g * KHALF))[k4] =
            ((const float4*)(x + (size_t)(b0 + g) * IN_ + kofs))[k4];
    }
    __syncthreads();

    for (int i = threadIdx.x; i < GROUP * (KHALF / 8); i += PTH) {
        int g = i >> 7, c8 = (i & 127) << 3;
        __nv_bfloat16 h[8], l[8];
        #pragma unroll
        for (int j = 0; j < 8; j++) split_bf16(xs[g * KHALF + c8 + j], h[j], l[j]);
        *(uint4*)(g_Ahi + (size_t)(b0 + g) * KO + kofs + c8) = *(const uint4*)h;
        *(uint4*)(g_Alo + (size_t)(b0 + g) * KO + kofs + c8) = *(const uint4*)l;
    }

    const int t  = threadIdx.x;
    const int c4 = t % CW4;
    const int kq = t / CW4;
    const int kbase = kq * KSLC;

    float4 acc[GROUP];
    #pragma unroll
    for (int g = 0; g < GROUP; g++) acc[g] = make_float4(0.f, 0.f, 0.f, 0.f);

    const float4* wp = (const float4*)(g_W + (size_t)(kofs + kbase) * NPAD) + c4;
    #pragma unroll 8
    for (int k = 0; k < KSLC; k++) {
        const float4 w = wp[(size_t)k * (NPAD / 4)];
        const int kk = kbase + k;
        #pragma unroll
        for (int g = 0; g < GROUP; g++) {
            const float xv = xs[g * KHALF + kk];
            acc[g].x = fmaf(xv, w.x, acc[g].x);
            acc[g].y = fmaf(xv, w.y, acc[g].y);
            acc[g].z = fmaf(xv, w.z, acc[g].z);
            acc[g].w = fmaf(xv, w.w, acc[g].w);
        }
    }
    #pragma unroll
    for (int g = 0; g < GROUP; g++)
        *(float4*)&red[(g * KQ2 + kq) * NPAD + c4 * 4] = acc[g];
    __syncthreads();

    if (t < 130) {
        #pragma unroll
        for (int g = 0; g < GROUP; g++) {
            float s = 0.f;
            #pragma unroll
            for (int q = 0; q < KQ2; q++)
                s += red[(g * KQ2 + q) * NPAD + t];
            const int b = b0 + g;
            if (t < 64)       atomicAdd(&g_q[(size_t)b * MEM_ + t], s);
            else if (t == 64) atomicAdd(&g_xf[b], s);
            else              atomicAdd(&g_xr[(size_t)b * RCOLS + (t - 65)], s);
        }
    }
}
#define PROJ_SMEM ((GROUP * KHALF + GROUP * KQ2 * NPAD) * 4)

// ==================================================================
// Kernel B: memory-fused, NO fp32 smem copy — memory reads go to
// gmem (L2-hot, 32KB/CTA). smem = images 53KB + tail -> 3 CTAs/SM.
// ==================================================================
#define MTH   256
// smem (floats): img [0, 13312) ; tail: qs 64|wpr 64|xrs 68|s1 128|
//   s2 128|red16 16|pad 512
#define TAIL_OFF 13312
#define MEM_SMEM ((TAIL_OFF + 1024) * 4)   // 57344 B

__device__ __forceinline__ void blockReduce2(
    float& va, float& vb, float* red16, int isSum)
{
    #pragma unroll
    for (int o = 16; o; o >>= 1) {
        float ua = __shfl_xor_sync(0xffffffffu, va, o);
        float ub = __shfl_xor_sync(0xffffffffu, vb, o);
        va = isSum ? (va + ua) : fmaxf(va, ua);
        vb = isSum ? (vb + ub) : fmaxf(vb, ub);
    }
    if ((threadIdx.x & 31) == 0) {
        red16[(threadIdx.x >> 5) * 2]     = va;
        red16[(threadIdx.x >> 5) * 2 + 1] = vb;
    }
    __syncthreads();
    float ra = red16[0], rb = red16[1];
    #pragma unroll
    for (int i = 1; i < 8; i++) {
        ra = isSum ? (ra + red16[2 * i])     : fmaxf(ra, red16[2 * i]);
        rb = isSum ? (rb + red16[2 * i + 1]) : fmaxf(rb, red16[2 * i + 1]);
    }
    __syncthreads();
    va = ra; vb = rb;
}

__global__ __launch_bounds__(MTH, 3) void mem_kernel(
    const float* __restrict__ memory,
    const float* __restrict__ W_pr, const float* __restrict__ b_pr,
    float* __restrict__ new_memory)
{
    extern __shared__ float sm[];
    char*  img   = (char*)sm;
    float* remS  = (float*)img;              // overlay (after all img reads)
    float* qs    = sm + TAIL_OFF;
    float* wpr   = qs + 64;
    float* xrs   = wpr + 64;                 // 68
    float* s1    = xrs + 68;
    float* s2    = s1 + 128;
    float* red16 = s2 + 128;                 // 16
    float* pad   = red16 + 16;               // 512

    const int b    = blockIdx.x;
    const int t    = threadIdx.x;
    const int wid  = t >> 5;
    const int lane = t & 31;
    const float* memb = memory + (size_t)b * NS * MEM_;
    const float xfv = g_xf[b];

    // ---- 1. gmem -> Ahi/Alo swizzled bf16 images ----
    {
        __nv_bfloat16* Ah = (__nv_bfloat16*)img;
        __nv_bfloat16* Al = (__nv_bfloat16*)(img + 16384);
        for (int i8 = t; i8 < NS * MEM_ / 8; i8 += MTH) {
            const int e = i8 * 8;
            const int n = e >> 6, q = (e & 63) >> 3;
            float4 v0 = *(const float4*)(memb + e);
            float4 v1 = *(const float4*)(memb + e + 4);
            const float vv[8] = {v0.x, v0.y, v0.z, v0.w, v1.x, v1.y, v1.z, v1.w};
            __nv_bfloat16 h[8], l[8];
            #pragma unroll
            for (int j = 0; j < 8; j++) split_bf16(vv[j], h[j], l[j]);
            const int idx = n * 64 + ((q ^ (n & 7)) << 3);
            *(uint4*)(Ah + idx) = *(const uint4*)h;
            *(uint4*)(Al + idx) = *(const uint4*)l;
        }
    }
    {
        const uint4* wbh = (const uint4*)g_WBhi;
        const uint4* wbl = (const uint4*)g_WBlo;
        uint4* Bh = (uint4*)(img + 32768);
        uint4* Bl = (uint4*)(img + 43008);
        for (int i = t; i < 1280; i += MTH) {
            if (i < 640) Bh[i] = wbh[i];
            else         Bl[i - 640] = wbl[i - 640];
        }
    }
    if (t < 64) { qs[t] = g_q[(size_t)b * MEM_ + t]; wpr[t] = W_pr[t]; }
    if (t < 65) { xrs[t] = g_xr[(size_t)b * RCOLS + t]; }
    __syncthreads();

    // ---- 2. rem GEMM (bf16-split, 3 products) ----
    const uint32_t Abase = smem_u32(img);
    const uint32_t Bbase = Abase + 32768;
    const int rr   = wid * 16;
    const int lrow = ((lane >> 3) & 1) * 8 + (lane & 7);
    const int lh   = (lane >> 4) & 1;

    float c[10][4];
    #pragma unroll
    for (int i = 0; i < 10; i++)
        #pragma unroll
        for (int q = 0; q < 4; q++) c[i][q] = 0.f;

    #pragma unroll
    for (int s = 0; s < 4; s++) {
        const int hb = s * 2 + lh;
        const int arow = rr + lrow;
        const uint32_t aoff = arow * 128 + ((hb ^ (arow & 7)) << 4);
        uint32_t ah[4], al[4];
        ldm_x4(ah, Abase + aoff);
        ldm_x4(al, Abase + 16384 + aoff);
        #pragma unroll
        for (int gp = 0; gp < 5; gp++) {
            const int jr = gp * 16 + lrow;
            const uint32_t boff = jr * 128 + ((hb ^ (jr & 7)) << 4);
            uint32_t r4[4], q4[4];
            ldm_x4(r4, Bbase + boff);
            ldm_x4(q4, Bbase + 10240 + boff);
            uint32_t bh0[2] = {r4[0], r4[2]}, bh1[2] = {r4[1], r4[3]};
            uint32_t bl0[2] = {q4[0], q4[2]}, bl1[2] = {q4[1], q4[3]};
            mma16816(c[gp * 2], ah, bh0);
            mma16816(c[gp * 2], ah, bl0);
            mma16816(c[gp * 2], al, bh0);
            mma16816(c[gp * 2 + 1], ah, bh1);
            mma16816(c[gp * 2 + 1], ah, bl1);
            mma16816(c[gp * 2 + 1], al, bh1);
        }
    }
    __syncthreads();

    // ---- 3. phase 1: scores from gmem (L2-hot), softmax ----
    float s1v = -1e30f, s2v = -1e30f;
    if (t < NS) {
        float a = 0.f, p = 0.f;
        #pragma unroll
        for (int k4 = 0; k4 < 16; k4++) {
            const float4 mv = __ldg((const float4*)(memb + t * MEM_ + k4 * 4));
            a = fmaf(mv.x, qs[k4 * 4 + 0], a);
            a = fmaf(mv.y, qs[k4 * 4 + 1], a);
            a = fmaf(mv.z, qs[k4 * 4 + 2], a);
            a = fmaf(mv.w, qs[k4 * 4 + 3], a);
            p = fmaf(mv.x, wpr[k4 * 4 + 0], p);
            p = fmaf(mv.y, wpr[k4 * 4 + 1], p);
            p = fmaf(mv.z, wpr[k4 * 4 + 2], p);
            p = fmaf(mv.w, wpr[k4 * 4 + 3], p);
        }
        s1v = a;
        s2v = p + b_pr[0];
    }
    float m1 = s1v, m2 = s2v;
    blockReduce2(m1, m2, red16, 0);
    float e1 = (t < NS) ? expf(s1v - m1) : 0.f;
    float e2 = (t < NS) ? expf(s2v - m2) : 0.f;
    float u1 = e1, u2 = e2;
    blockReduce2(u1, u2, red16, 1);
    if (t < NS) { s1[t] = e1 / u1; s2[t] = e2 / u2; }
    __syncthreads();

    // ---- act/pas from gmem (coalesced columns) ----
    {
        const int col = t & 63;
        const int grp = t >> 6;
        float act = 0.f, pas = 0.f;
        #pragma unroll 4
        for (int n = grp * 32; n < grp * 32 + 32; n++) {
            float mv = __ldg(memb + n * MEM_ + col);
            act = fmaf(s1[n], mv, act);
            pas = fmaf(s2[n], mv, pas);
        }
        pad[grp * 64 + col]       = act;
        pad[256 + grp * 64 + col] = pas;
    }
    __syncthreads();
    if (t < MEM_) {
        float act = pad[t] + pad[64 + t] + pad[128 + t] + pad[192 + t];
        float pas = pad[256 + t] + pad[320 + t] + pad[384 + t] + pad[448 + t];
        __nv_bfloat16 h, l;
        split_bf16(act, h, l);
        g_Ahi[(size_t)b * KO + IN_ + t] = h;
        g_Alo[(size_t)b * KO + IN_ + t] = l;
        split_bf16(pas, h, l);
        g_Ahi[(size_t)b * KO + IN_ + MEM_ + t] = h;
        g_Alo[(size_t)b * KO + IN_ + MEM_ + t] = l;
    }
    __syncthreads();   // all img reads done; safe to fill remS

    // ---- 4. rem frags (+bias, sigmoid col 65) -> remS ----
    {
        const int g  = lane >> 2;
        const int tg = lane & 3;
        const int r0 = rr + g;
        #pragma unroll
        for (int nf = 0; nf < 10; nf++) {
            const int col = nf * 8 + tg * 2;
            #pragma unroll
            for (int half = 0; half < 2; half++) {
                const int cc = col + half;
                if (cc > 65) continue;
                const float bias = (cc < 65) ? xrs[cc] : 0.f;
                float v0 = c[nf][half]     + bias;
                float v1 = c[nf][half + 2] + bias;
                if (cc == 65) {
                    v0 = 1.1f / (1.f + expf(-(v0 + xfv)));
                    v1 = 1.1f / (1.f + expf(-(v1 + xfv)));
                }
                remS[r0 * 72 + cc]       = v0;
                remS[(r0 + 8) * 72 + cc] = v1;
            }
        }
    }
    __syncthreads();

    // ---- 5. gating (memory re-read from gmem, coalesced) ----
    float* nm = new_memory + (size_t)b * NS * MEM_;
    for (int i4 = t; i4 < NS * MEM_ / 4; i4 += MTH) {
        int e = i4 * 4;
        int n = e >> 6, m = e & 63;
        const float f    = remS[n * 72 + 65];
        const float gate = remS[n * 72 + 64];
        float4 mv = __ldg((const float4*)(memb + e));
        float4 rv = *(float4*)&remS[n * 72 + m];
        float4 o;
        o.x = fmaf(mv.x, f, gate * rv.x);
        o.y = fmaf(mv.y, f, gate * rv.y);
        o.z = fmaf(mv.z, f, gate * rv.z);
        o.w = fmaf(mv.w, f, gate * rv.w);
        *(float4*)(nm + e) = o;
    }
}

// ==================================================================
// Kernel C: mma.sync bf16-split GEMM, 4-stage ring, prefetch dist 2,
// one __syncthreads per chunk (unchanged from R13/R14).
// ==================================================================
#define CTA_M   64
#define CTA_N   128
#define KCHUNK  32
#define NKC     68
#define A_TB    4096
#define B_TB    8192
#define STAGE_B (2 * A_TB + 2 * B_TB)
#define GEMM_SMEM (4 * STAGE_B)

__device__ __forceinline__ uint32_t swz64(int r, int h) {
    return (uint32_t)((h ^ (r & 3) ^ ((r >> 2) & 1)) << 4);
}

__device__ __forceinline__ void gemm_prefetch(
    uint32_t smem, int tid, int br, int bc, int k0, int stage)
{
    const uint32_t sb = smem + stage * STAGE_B;
    #pragma unroll
    for (int q = 0; q < 2; q++) {
        int u = tid + q * 256;
        int tile = u >> 8, rm = u & 255;
        int r = rm >> 2, h = rm & 3;
        const __nv_bfloat16* src =
            (tile ? g_Alo : g_Ahi) + (size_t)(br + r) * KO + k0 + h * 8;
        cp16(sb + tile * A_TB + r * 64 + swz64(r, h), src);
    }
    #pragma unroll
    for (int q = 0; q < 4; q++) {
        int u = tid + q * 256;
        int tile = u >> 9, rm = u & 511;
        int n = rm >> 2, h = rm & 3;
        const __nv_bfloat16* src =
            (tile ? g_Blo : g_Bhi) + (size_t)(bc + n) * KO + k0 + h * 8;
        cp16(sb + 2 * A_TB + tile * B_TB + n * 64 + swz64(n, h), src);
    }
    CP_COMMIT();
}

__device__ __forceinline__ void gemm_chunk(
    uint32_t sb, int wm, int wn, int lrow, int lh, float c[2][4][4])
{
    #pragma unroll
    for (int s = 0; s < 2; s++) {
        const int h = s * 2 + lh;
        uint32_t ah[2][4], al[2][4];
        #pragma unroll
        for (int f = 0; f < 2; f++) {
            int rr = wm * 32 + f * 16 + lrow;
            ldm_x4(ah[f], sb + rr * 64 + swz64(rr, h));
            ldm_x4(al[f], sb + A_TB + rr * 64 + swz64(rr, h));
        }
        uint32_t bh[4][2], bl[4][2];
        #pragma unroll
        for (int jj = 0; jj < 2; jj++) {
            int nn = wn * 32 + jj * 16 + lrow;
            uint32_t r4[4];
            ldm_x4(r4, sb + 2 * A_TB + nn * 64 + swz64(nn, h));
            bh[2 * jj][0] = r4[0]; bh[2 * jj + 1][0] = r4[1];
            bh[2 * jj][1] = r4[2]; bh[2 * jj + 1][1] = r4[3];
            ldm_x4(r4, sb + 2 * A_TB + B_TB + nn * 64 + swz64(nn, h));
            bl[2 * jj][0] = r4[0]; bl[2 * jj + 1][0] = r4[1];
            bl[2 * jj][1] = r4[2]; bl[2 * jj + 1][1] = r4[3];
        }
        #pragma unroll
        for (int mf = 0; mf < 2; mf++)
            #pragma unroll
            for (int nf = 0; nf < 4; nf++) {
                mma16816(c[mf][nf], ah[mf], bh[nf]);
                mma16816(c[mf][nf], ah[mf], bl[nf]);
                mma16816(c[mf][nf], al[mf], bh[nf]);
            }
    }
}

__global__ __launch_bounds__(256) void out_gemm_mma(
    const float* __restrict__ b_o, float* __restrict__ out)
{
    extern __shared__ __align__(128) char gsm[];
    const int tid  = threadIdx.x;
    const int wid  = tid >> 5;
    const int lane = tid & 31;
    const int wm   = wid & 1;
    const int wn   = wid >> 1;
    const int br   = blockIdx.y * CTA_M;
    const int bc   = blockIdx.x * CTA_N;
    const uint32_t smem = smem_u32(gsm);

    float c[2][4][4];
    #pragma unroll
    for (int i = 0; i < 2; i++)
        #pragma unroll
        for (int j = 0; j < 4; j++)
            #pragma unroll
            for (int q = 0; q < 4; q++) c[i][j][q] = 0.f;

    const int lrow = ((lane >> 3) & 1) * 8 + (lane & 7);
    const int lh   = (lane >> 4) & 1;

    gemm_prefetch(smem, tid, br, bc, 0 * KCHUNK, 0);
    gemm_prefetch(smem, tid, br, bc, 1 * KCHUNK, 1);

    for (int kc = 0; kc < NKC; kc++) {
        if (kc + 2 < NKC) { gemm_prefetch(smem, tid, br, bc, (kc + 2) * KCHUNK, (kc + 2) & 3); CP_WAIT(2); }
        else if (kc + 1 < NKC) { CP_WAIT(1); }
        else { CP_WAIT(0); }
        __syncthreads();
        gemm_chunk(smem + (kc & 3) * STAGE_B, wm, wn, lrow, lh, c);
    }

    const int g  = lane >> 2;
    const int tg = lane & 3;
    #pragma unroll
    for (int nf = 0; nf < 4; nf++) {
        const int col = bc + wn * 32 + nf * 8 + tg * 2;
        const float2 bb = *(const float2*)(b_o + col);
        #pragma unroll
        for (int mf = 0; mf < 2; mf++) {
            const int row0 = br + wm * 32 + mf * 16 + g;
            float2 v0 = make_float2(c[mf][nf][0] + bb.x, c[mf][nf][1] + bb.y);
            float2 v1 = make_float2(c[mf][nf][2] + bb.x, c[mf][nf][3] + bb.y);
            *(float2*)(out + (size_t)row0 * OUT_ + col)       = v0;
            *(float2*)(out + (size_t)(row0 + 8) * OUT_ + col) = v1;
        }
    }
}

// ==================================================================
// Launch
// ==================================================================
extern "C" void kernel_launch(void* const* d_in, const int* in_sizes, int n_in,
                              void* d_out, int out_size)
{
    const float* x    = (const float*)d_in[0];
    const float* mem  = (const float*)d_in[1];
    const float* W_ar = (const float*)d_in[2];
    const float* b_ar = (const float*)d_in[3];
    const float* W_pr = (const float*)d_in[4];
    const float* b_pr = (const float*)d_in[5];
    const float* W_f  = (const float*)d_in[6];
    const float* b_f  = (const float*)d_in[7];
    const float* W_r  = (const float*)d_in[8];
    const float* b_r  = (const float*)d_in[9];
    const float* W_o  = (const float*)d_in[10];
    const float* b_o  = (const float*)d_in[11];

    float* out     = (float*)d_out;
    float* new_mem = out + (size_t)B_ * OUT_;

    static cudaStream_t s1 = nullptr;
    static cudaEvent_t ev_root = nullptr, ev_side = nullptr;
    if (!s1) {
        cudaStreamCreateWithFlags(&s1, cudaStreamNonBlocking);
        cudaEventCreateWithFlags(&ev_root, cudaEventDisableTiming);
        cudaEventCreateWithFlags(&ev_side, cudaEventDisableTiming);
        cudaFuncSetAttribute(mem_kernel, cudaFuncAttributeMaxDynamicSharedMemorySize, MEM_SMEM);
        cudaFuncSetAttribute(proj_kernel, cudaFuncAttributeMaxDynamicSharedMemorySize, PROJ_SMEM);
        cudaFuncSetAttribute(out_gemm_mma, cudaFuncAttributeMaxDynamicSharedMemorySize, GEMM_SMEM);
    }

    // fork: conv_B on side stream
    cudaEventRecord(ev_root, 0);
    cudaStreamWaitEvent(s1, ev_root, 0);
    {
        dim3 g(KO / 32, OUT_ / 32);
        conv_B_kernel<<<g, 256, 0, s1>>>(W_o);
    }
    cudaEventRecord(ev_side, s1);

    // main chain
    pack_kernel<<<(P_XR + 255) / 256, 256>>>(W_ar, W_f, W_r, b_ar, b_f, b_r);
    {
        dim3 g(B_ / GROUP, 2);
        proj_kernel<<<g, PTH, PROJ_SMEM>>>(x);
    }
    mem_kernel<<<B_, MTH, MEM_SMEM>>>(mem, W_pr, b_pr, new_mem);

    // join, then GEMM
    cudaStreamWaitEvent(0, ev_side, 0);
    {
        dim3 g(OUT_ / CTA_N, B_ / CTA_M);
        out_gemm_mma<<<g, 256, GEMM_SMEM>>>(b_o, out);
    }
}

// round 16
// speedup vs baseline: 1.0595x; 1.0595x over previous
#include <cuda_runtime.h>
#include <cuda_bf16.h>
#include <math.h>
#include <cstdint>

// Problem constants
#define B_    512
#define NS    128
#define IN_   2048
#define MEM_  64
#define OUT_  2048
#define RCOLS 65
#define KO    2176          // IN_ + 2*MEM_
#define NPAD  132

// ------------------------------------------------------------------
// Scratch (device globals)
// ------------------------------------------------------------------
__device__ float g_q  [B_ * MEM_];      // bias-init by pack, atomicAdd by proj
__device__ float g_xf [B_];
__device__ float g_xr [B_ * RCOLS];
__device__ float g_W  [IN_ * NPAD];
__device__ __nv_bfloat16 g_Ahi[B_ * KO];
__device__ __nv_bfloat16 g_Alo[B_ * KO];
__device__ __nv_bfloat16 g_Bhi[OUT_ * KO];
__device__ __nv_bfloat16 g_Blo[OUT_ * KO];
__device__ __nv_bfloat16 g_WBhi[80 * 64];
__device__ __nv_bfloat16 g_WBlo[80 * 64];

// ------------------------------------------------------------------
// Helpers
// ------------------------------------------------------------------
__device__ __forceinline__ uint32_t smem_u32(const void* p) {
    uint32_t a;
    asm("{ .reg .u64 t; cvta.to.shared.u64 t, %1; cvt.u32.u64 %0, t; }"
        : "=r"(a) : "l"(p));
    return a;
}
__device__ __forceinline__ void cp16(uint32_t dst, const void* src) {
    asm volatile("cp.async.cg.shared.global [%0], [%1], 16;" :: "r"(dst), "l"(src));
}
#define CP_COMMIT()  asm volatile("cp.async.commit_group;" ::: "memory")
#define CP_WAIT(n)   asm volatile("cp.async.wait_group %0;" :: "n"(n) : "memory")

__device__ __forceinline__ void ldm_x4(uint32_t* r, uint32_t addr) {
    asm volatile("ldmatrix.sync.aligned.m8n8.x4.shared.b16 {%0,%1,%2,%3}, [%4];"
        : "=r"(r[0]), "=r"(r[1]), "=r"(r[2]), "=r"(r[3]) : "r"(addr));
}
__device__ __forceinline__ void mma16816(float* c, const uint32_t* a, const uint32_t* b) {
    asm volatile(
        "mma.sync.aligned.m16n8k16.row.col.f32.bf16.bf16.f32 "
        "{%0,%1,%2,%3}, {%4,%5,%6,%7}, {%8,%9}, {%0,%1,%2,%3};"
        : "+f"(c[0]), "+f"(c[1]), "+f"(c[2]), "+f"(c[3])
        : "r"(a[0]), "r"(a[1]), "r"(a[2]), "r"(a[3]), "r"(b[0]), "r"(b[1]));
}
__device__ __forceinline__ void split_bf16(float v, __nv_bfloat16& h, __nv_bfloat16& l) {
    h = __float2bfloat16(v);
    l = __float2bfloat16(v - __bfloat162float(h));
}

// ==================================================================
// Prep: pack weights + bias-init the projection accumulators.
// ==================================================================
#define P_W    (IN_ * NPAD)
#define P_WB   (P_W + 80 * 64)
#define P_Q    (P_WB + B_ * MEM_)
#define P_XF   (P_Q + B_)
#define P_XR   (P_XF + B_ * RCOLS)
__global__ __launch_bounds__(256) void pack_kernel(
    const float* __restrict__ W_ar, const float* __restrict__ W_f,
    const float* __restrict__ W_r,
    const float* __restrict__ b_ar, const float* __restrict__ b_f,
    const float* __restrict__ b_r)
{
    int idx = blockIdx.x * 256 + threadIdx.x;
    if (idx >= P_XR) return;
    if (idx < P_W) {
        int k = idx / NPAD, c = idx - k * NPAD;
        float v = 0.f;
        if (c < 64)       v = W_ar[(size_t)k * 64 + c];
        else if (c == 64) v = W_f[k];
        else if (c < 130) v = W_r[(size_t)k * RCOLS + (c - 65)];
        g_W[idx] = v;
    } else if (idx < P_WB) {
        int e = idx - P_W;
        int j = e >> 6, k = e & 63;
        float v = 0.f;
        if (j < 65)       v = W_r[(size_t)(IN_ + k) * RCOLS + j];
        else if (j == 65) v = W_f[IN_ + k];
        __nv_bfloat16 h, l;
        split_bf16(v, h, l);
        int dst = j * 64 + (((k >> 3) ^ (j & 7)) << 3) + (k & 7);
        g_WBhi[dst] = h;
        g_WBlo[dst] = l;
    } else if (idx < P_Q) {
        int e = idx - P_WB;
        g_q[e] = b_ar[e & 63];
    } else if (idx < P_XF) {
        g_xf[idx - P_Q] = b_f[0];
    } else {
        int e = idx - P_XF;
        g_xr[e] = b_r[e % RCOLS];
    }
}

// W_o [K=2176][N=2048] -> g_B* [N][K] bf16 hi/lo (tiled transpose)
__global__ __launch_bounds__(256) void conv_B_kernel(const float* __restrict__ W_o)
{
    __shared__ float t[32][33];
    const int k0 = blockIdx.x * 32;
    const int n0 = blockIdx.y * 32;
    const int tid = threadIdx.x;
    #pragma unroll
    for (int p = 0; p < 4; p++) {
        int r = (tid >> 5) + p * 8, c = tid & 31;
        t[r][c] = W_o[(size_t)(k0 + r) * OUT_ + n0 + c];
    }
    __syncthreads();
    #pragma unroll
    for (int p = 0; p < 2; p++) {
        int r = (tid >> 4) + p * 16;
        int cc = (tid & 15) * 2;
        float v0 = t[cc][r], v1 = t[cc + 1][r];
        __nv_bfloat16 h0, l0, h1, l1;
        split_bf16(v0, h0, l0);
        split_bf16(v1, h1, l1);
        __nv_bfloat162 hp; hp.x = h0; hp.y = h1;
        __nv_bfloat162 lp; lp.x = l0; lp.y = l1;
        *(__nv_bfloat162*)(g_Bhi + (size_t)(n0 + r) * KO + k0 + cc) = hp;
        *(__nv_bfloat162*)(g_Blo + (size_t)(n0 + r) * KO + k0 + cc) = lp;
    }
}

// ==================================================================
// Kernel A: projections, GROUP=8 x 2 k-halves, atomic combine.
// ==================================================================
#define GROUP 8
#define KHALF (IN_ / 2)
#define CW4   33
#define KQ2   16
#define PTH   (CW4 * KQ2)
#define KSLC  (KHALF / KQ2)

__global__ __launch_bounds__(PTH) void proj_kernel(const float* __restrict__ x)
{
    extern __shared__ float psm[];
    float* xs  = psm;
    float* red = psm + GROUP * KHALF;
    const int b0 = blockIdx.x * GROUP;
    const int kh = blockIdx.y;
    const int kofs = kh * KHALF;

    for (int i = threadIdx.x; i < GROUP * (KHALF / 4); i += PTH) {
        int g = i >> 8, k4 = i & 255;
        ((float4*)(xs + g * KHALF))[k4] =
            ((const float4*)(x + (size_t)(b0 + g) * IN_ + kofs))[k4];
    }
    __syncthreads();

    for (int i = threadIdx.x; i < GROUP * (KHALF / 8); i += PTH) {
        int g = i >> 7, c8 = (i & 127) << 3;
        __nv_bfloat16 h[8], l[8];
        #pragma unroll
        for (int j = 0; j < 8; j++) split_bf16(xs[g * KHALF + c8 + j], h[j], l[j]);
        *(uint4*)(g_Ahi + (size_t)(b0 + g) * KO + kofs + c8) = *(const uint4*)h;
        *(uint4*)(g_Alo + (size_t)(b0 + g) * KO + kofs + c8) = *(const uint4*)l;
    }

    const int t  = threadIdx.x;
    const int c4 = t % CW4;
    const int kq = t / CW4;
    const int kbase = kq * KSLC;

    float4 acc[GROUP];
    #pragma unroll
    for (int g = 0; g < GROUP; g++) acc[g] = make_float4(0.f, 0.f, 0.f, 0.f);

    const float4* wp = (const float4*)(g_W + (size_t)(kofs + kbase) * NPAD) + c4;
    #pragma unroll 8
    for (int k = 0; k < KSLC; k++) {
        const float4 w = wp[(size_t)k * (NPAD / 4)];
        const int kk = kbase + k;
        #pragma unroll
        for (int g = 0; g < GROUP; g++) {
            const float xv = xs[g * KHALF + kk];
            acc[g].x = fmaf(xv, w.x, acc[g].x);
            acc[g].y = fmaf(xv, w.y, acc[g].y);
            acc[g].z = fmaf(xv, w.z, acc[g].z);
            acc[g].w = fmaf(xv, w.w, acc[g].w);
        }
    }
    #pragma unroll
    for (int g = 0; g < GROUP; g++)
        *(float4*)&red[(g * KQ2 + kq) * NPAD + c4 * 4] = acc[g];
    __syncthreads();

    if (t < 130) {
        #pragma unroll
        for (int g = 0; g < GROUP; g++) {
            float s = 0.f;
            #pragma unroll
            for (int q = 0; q < KQ2; q++)
                s += red[(g * KQ2 + q) * NPAD + t];
            const int b = b0 + g;
            if (t < 64)       atomicAdd(&g_q[(size_t)b * MEM_ + t], s);
            else if (t == 64) atomicAdd(&g_xf[b], s);
            else              atomicAdd(&g_xr[(size_t)b * RCOLS + (t - 65)], s);
        }
    }
}
#define PROJ_SMEM ((GROUP * KHALF + GROUP * KQ2 * NPAD) * 4)

// ==================================================================
// Kernel B: memory-fused, shortened phase chain:
//   load(+inline scores via shfl) -> MMA -> register gating ->
//   softmax -> act/pas. No remS pass, no separate score pass.
// ==================================================================
#define MTH   256
#define MSP   68
// smem (floats): msf [0,8704) | img [8704, 8704+13312) | tail
#define TAIL_OFF (8704 + 13312)
#define MEM_SMEM ((TAIL_OFF + 1024) * 4)

__device__ __forceinline__ void blockReduce2(
    float& va, float& vb, float* red16, int isSum)
{
    #pragma unroll
    for (int o = 16; o; o >>= 1) {
        float ua = __shfl_xor_sync(0xffffffffu, va, o);
        float ub = __shfl_xor_sync(0xffffffffu, vb, o);
        va = isSum ? (va + ua) : fmaxf(va, ua);
        vb = isSum ? (vb + ub) : fmaxf(vb, ub);
    }
    if ((threadIdx.x & 31) == 0) {
        red16[(threadIdx.x >> 5) * 2]     = va;
        red16[(threadIdx.x >> 5) * 2 + 1] = vb;
    }
    __syncthreads();
    float ra = red16[0], rb = red16[1];
    #pragma unroll
    for (int i = 1; i < 8; i++) {
        ra = isSum ? (ra + red16[2 * i])     : fmaxf(ra, red16[2 * i]);
        rb = isSum ? (rb + red16[2 * i + 1]) : fmaxf(rb, red16[2 * i + 1]);
    }
    __syncthreads();
    va = ra; vb = rb;
}

__global__ __launch_bounds__(MTH) void mem_kernel(
    const float* __restrict__ memory,
    const float* __restrict__ W_pr, const float* __restrict__ b_pr,
    float* __restrict__ new_memory)
{
    extern __shared__ float sm[];
    float* msf   = sm;                       // 128 x 68
    char*  img   = (char*)(sm + 8704);       // Ahi 16K | Alo 16K | Bhi 10K | Blo 10K
    float* qs    = sm + TAIL_OFF;
    float* wpr   = qs + 64;
    float* xrs   = wpr + 64;                 // 68
    float* s1    = xrs + 68;
    float* s2    = s1 + 128;
    float* red16 = s2 + 128;                 // 16
    float* pad   = red16 + 16;               // 512 (raw scores then act/pas partials)

    const int b    = blockIdx.x;
    const int t    = threadIdx.x;
    const int wid  = t >> 5;
    const int lane = t & 31;
    const float* memb = memory + (size_t)b * NS * MEM_;
    const float xfv = g_xf[b];

    if (t < 64) { qs[t] = g_q[(size_t)b * MEM_ + t]; wpr[t] = W_pr[t]; }
    if (t < 65) { xrs[t] = g_xr[(size_t)b * RCOLS + t]; }
    __syncthreads();

    // ---- 1. fused load: gmem -> msf + bf16 images + inline scores ----
    {
        __nv_bfloat16* Ah = (__nv_bfloat16*)img;
        __nv_bfloat16* Al = (__nv_bfloat16*)(img + 16384);
        #pragma unroll
        for (int it = 0; it < 4; it++) {                 // 1024 chunks / 256 thr
            const int i8 = t + it * MTH;
            const int e = i8 * 8;
            const int n = e >> 6, m = e & 63, q = m >> 3;
            float4 v0 = *(const float4*)(memb + e);
            float4 v1 = *(const float4*)(memb + e + 4);
            *(float4*)&msf[n * MSP + m]     = v0;
            *(float4*)&msf[n * MSP + m + 4] = v1;
            const float vv[8] = {v0.x, v0.y, v0.z, v0.w, v1.x, v1.y, v1.z, v1.w};
            __nv_bfloat16 h[8], l[8];
            #pragma unroll
            for (int j = 0; j < 8; j++) split_bf16(vv[j], h[j], l[j]);
            const int idx = n * 64 + ((q ^ (n & 7)) << 3);
            *(uint4*)(Ah + idx) = *(const uint4*)h;
            *(uint4*)(Al + idx) = *(const uint4*)l;
            // inline partial scores for row n over cols m..m+7
            float pa = 0.f, pp = 0.f;
            #pragma unroll
            for (int j = 0; j < 8; j++) {
                pa = fmaf(vv[j], qs[m + j], pa);
                pp = fmaf(vv[j], wpr[m + j], pp);
            }
            pa += __shfl_xor_sync(0xffffffffu, pa, 1);
            pp += __shfl_xor_sync(0xffffffffu, pp, 1);
            pa += __shfl_xor_sync(0xffffffffu, pa, 2);
            pp += __shfl_xor_sync(0xffffffffu, pp, 2);
            pa += __shfl_xor_sync(0xffffffffu, pa, 4);
            pp += __shfl_xor_sync(0xffffffffu, pp, 4);
            if ((t & 7) == 0) { pad[n] = pa; pad[128 + n] = pp; }
        }
    }
    {
        const uint4* wbh = (const uint4*)g_WBhi;
        const uint4* wbl = (const uint4*)g_WBlo;
        uint4* Bh = (uint4*)(img + 32768);
        uint4* Bl = (uint4*)(img + 43008);
        for (int i = t; i < 1280; i += MTH) {
            if (i < 640) Bh[i] = wbh[i];
            else         Bl[i - 640] = wbl[i - 640];
        }
    }
    __syncthreads();

    // ---- 2. rem GEMM (bf16-split, 3 products) ----
    const uint32_t Abase = smem_u32(img);
    const uint32_t Bbase = Abase + 32768;
    const int rr   = wid * 16;
    const int lrow = ((lane >> 3) & 1) * 8 + (lane & 7);
    const int lh   = (lane >> 4) & 1;

    float c[10][4];
    #pragma unroll
    for (int i = 0; i < 10; i++)
        #pragma unroll
        for (int q = 0; q < 4; q++) c[i][q] = 0.f;

    #pragma unroll
    for (int s = 0; s < 4; s++) {
        const int hb = s * 2 + lh;
        const int arow = rr + lrow;
        const uint32_t aoff = arow * 128 + ((hb ^ (arow & 7)) << 4);
        uint32_t ah[4], al[4];
        ldm_x4(ah, Abase + aoff);
        ldm_x4(al, Abase + 16384 + aoff);
        #pragma unroll
        for (int gp = 0; gp < 5; gp++) {
            const int jr = gp * 16 + lrow;
            const uint32_t boff = jr * 128 + ((hb ^ (jr & 7)) << 4);
            uint32_t r4[4], q4[4];
            ldm_x4(r4, Bbase + boff);
            ldm_x4(q4, Bbase + 10240 + boff);
            uint32_t bh0[2] = {r4[0], r4[2]}, bh1[2] = {r4[1], r4[3]};
            uint32_t bl0[2] = {q4[0], q4[2]}, bl1[2] = {q4[1], q4[3]};
            mma16816(c[gp * 2], ah, bh0);
            mma16816(c[gp * 2], ah, bl0);
            mma16816(c[gp * 2], al, bh0);
            mma16816(c[gp * 2 + 1], ah, bh1);
            mma16816(c[gp * 2 + 1], ah, bl1);
            mma16816(c[gp * 2 + 1], al, bh1);
        }
    }

    // ---- 3. gating: rem fragments live in registers; gate/forget via
    //         quad broadcast (cols 64/65 sit at tg==0, nf==8). ----
    {
        const int g  = lane >> 2;
        const int tg = lane & 3;
        const int base = lane & ~3;
        const int row0 = rr + g;
        const int row1 = row0 + 8;

        const float gate0 = __shfl_sync(0xffffffffu, c[8][0], base) + xrs[64];
        const float fr0   = __shfl_sync(0xffffffffu, c[8][1], base);
        const float gate1 = __shfl_sync(0xffffffffu, c[8][2], base) + xrs[64];
        const float fr1   = __shfl_sync(0xffffffffu, c[8][3], base);
        const float f0 = 1.1f / (1.f + expf(-(fr0 + xfv)));
        const float f1 = 1.1f / (1.f + expf(-(fr1 + xfv)));

        float* nm = new_memory + (size_t)b * NS * MEM_;
        #pragma unroll
        for (int nf = 0; nf < 8; nf++) {
            const int col = nf * 8 + tg * 2;
            const float bx = xrs[col], by = xrs[col + 1];
            float2 o0, o1;
            o0.x = fmaf(msf[row0 * MSP + col],     f0, gate0 * (c[nf][0] + bx));
            o0.y = fmaf(msf[row0 * MSP + col + 1], f0, gate0 * (c[nf][1] + by));
            o1.x = fmaf(msf[row1 * MSP + col],     f1, gate1 * (c[nf][2] + bx));
            o1.y = fmaf(msf[row1 * MSP + col + 1], f1, gate1 * (c[nf][3] + by));
            *(float2*)(nm + row0 * MEM_ + col) = o0;
            *(float2*)(nm + row1 * MEM_ + col) = o1;
        }
    }

    // ---- 4. softmax (raw scores already in pad) ----
    float s1v = -1e30f, s2v = -1e30f;
    if (t < NS) {
        s1v = pad[t];
        s2v = pad[128 + t] + b_pr[0];
    }
    float m1 = s1v, m2 = s2v;
    blockReduce2(m1, m2, red16, 0);
    float e1 = (t < NS) ? expf(s1v - m1) : 0.f;
    float e2 = (t < NS) ? expf(s2v - m2) : 0.f;
    float u1 = e1, u2 = e2;
    blockReduce2(u1, u2, red16, 1);
    if (t < NS) { s1[t] = e1 / u1; s2[t] = e2 / u2; }
    __syncthreads();

    // ---- 5. act/pas (msf columns), combine, store bf16 hi/lo ----
    {
        const int col = t & 63;
        const int grp = t >> 6;
        float act = 0.f, pas = 0.f;
        #pragma unroll 4
        for (int n = grp * 32; n < grp * 32 + 32; n++) {
            float mv = msf[n * MSP + col];
            act = fmaf(s1[n], mv, act);
            pas = fmaf(s2[n], mv, pas);
        }
        pad[grp * 64 + col]       = act;
        pad[256 + grp * 64 + col] = pas;
    }
    __syncthreads();
    if (t < MEM_) {
        float act = pad[t] + pad[64 + t] + pad[128 + t] + pad[192 + t];
        float pas = pad[256 + t] + pad[320 + t] + pad[384 + t] + pad[448 + t];
        __nv_bfloat16 h, l;
        split_bf16(act, h, l);
        g_Ahi[(size_t)b * KO + IN_ + t] = h;
        g_Alo[(size_t)b * KO + IN_ + t] = l;
        split_bf16(pas, h, l);
        g_Ahi[(size_t)b * KO + IN_ + MEM_ + t] = h;
        g_Alo[(size_t)b * KO + IN_ + MEM_ + t] = l;
    }
}

// ==================================================================
// Kernel C: mma.sync bf16-split GEMM, 4-stage ring, prefetch dist 2,
// one __syncthreads per chunk (unchanged from R13/R14).
// ==================================================================
#define CTA_M   64
#define CTA_N   128
#define KCHUNK  32
#define NKC     68
#define A_TB    4096
#define B_TB    8192
#define STAGE_B (2 * A_TB + 2 * B_TB)
#define GEMM_SMEM (4 * STAGE_B)

__device__ __forceinline__ uint32_t swz64(int r, int h) {
    return (uint32_t)((h ^ (r & 3) ^ ((r >> 2) & 1)) << 4);
}

__device__ __forceinline__ void gemm_prefetch(
    uint32_t smem, int tid, int br, int bc, int k0, int stage)
{
    const uint32_t sb = smem + stage * STAGE_B;
    #pragma unroll
    for (int q = 0; q < 2; q++) {
        int u = tid + q * 256;
        int tile = u >> 8, rm = u & 255;
        int r = rm >> 2, h = rm & 3;
        const __nv_bfloat16* src =
            (tile ? g_Alo : g_Ahi) + (size_t)(br + r) * KO + k0 + h * 8;
        cp16(sb + tile * A_TB + r * 64 + swz64(r, h), src);
    }
    #pragma unroll
    for (int q = 0; q < 4; q++) {
        int u = tid + q * 256;
        int tile = u >> 9, rm = u & 511;
        int n = rm >> 2, h = rm & 3;
        const __nv_bfloat16* src =
            (tile ? g_Blo : g_Bhi) + (size_t)(bc + n) * KO + k0 + h * 8;
        cp16(sb + 2 * A_TB + tile * B_TB + n * 64 + swz64(n, h), src);
    }
    CP_COMMIT();
}

__device__ __forceinline__ void gemm_chunk(
    uint32_t sb, int wm, int wn, int lrow, int lh, float c[2][4][4])
{
    #pragma unroll
    for (int s = 0; s < 2; s++) {
        const int h = s * 2 + lh;
        uint32_t ah[2][4], al[2][4];
        #pragma unroll
        for (int f = 0; f < 2; f++) {
            int rr = wm * 32 + f * 16 + lrow;
            ldm_x4(ah[f], sb + rr * 64 + swz64(rr, h));
            ldm_x4(al[f], sb + A_TB + rr * 64 + swz64(rr, h));
        }
        uint32_t bh[4][2], bl[4][2];
        #pragma unroll
        for (int jj = 0; jj < 2; jj++) {
            int nn = wn * 32 + jj * 16 + lrow;
            uint32_t r4[4];
            ldm_x4(r4, sb + 2 * A_TB + nn * 64 + swz64(nn, h));
            bh[2 * jj][0] = r4[0]; bh[2 * jj + 1][0] = r4[1];
            bh[2 * jj][1] = r4[2]; bh[2 * jj + 1][1] = r4[3];
            ldm_x4(r4, sb + 2 * A_TB + B_TB + nn * 64 + swz64(nn, h));
            bl[2 * jj][0] = r4[0]; bl[2 * jj + 1][0] = r4[1];
            bl[2 * jj][1] = r4[2]; bl[2 * jj + 1][1] = r4[3];
        }
        #pragma unroll
        for (int mf = 0; mf < 2; mf++)
            #pragma unroll
            for (int nf = 0; nf < 4; nf++) {
                mma16816(c[mf][nf], ah[mf], bh[nf]);
                mma16816(c[mf][nf], ah[mf], bl[nf]);
                mma16816(c[mf][nf], al[mf], bh[nf]);
            }
    }
}

__global__ __launch_bounds__(256) void out_gemm_mma(
    const float* __restrict__ b_o, float* __restrict__ out)
{
    extern __shared__ __align__(128) char gsm[];
    const int tid  = threadIdx.x;
    const int wid  = tid >> 5;
    const int lane = tid & 31;
    const int wm   = wid & 1;
    const int wn   = wid >> 1;
    const int br   = blockIdx.y * CTA_M;
    const int bc   = blockIdx.x * CTA_N;
    const uint32_t smem = smem_u32(gsm);

    float c[2][4][4];
    #pragma unroll
    for (int i = 0; i < 2; i++)
        #pragma unroll
        for (int j = 0; j < 4; j++)
            #pragma unroll
            for (int q = 0; q < 4; q++) c[i][j][q] = 0.f;

    const int lrow = ((lane >> 3) & 1) * 8 + (lane & 7);
    const int lh   = (lane >> 4) & 1;

    gemm_prefetch(smem, tid, br, bc, 0 * KCHUNK, 0);
    gemm_prefetch(smem, tid, br, bc, 1 * KCHUNK, 1);

    for (int kc = 0; kc < NKC; kc++) {
        if (kc + 2 < NKC) { gemm_prefetch(smem, tid, br, bc, (kc + 2) * KCHUNK, (kc + 2) & 3); CP_WAIT(2); }
        else if (kc + 1 < NKC) { CP_WAIT(1); }
        else { CP_WAIT(0); }
        __syncthreads();
        gemm_chunk(smem + (kc & 3) * STAGE_B, wm, wn, lrow, lh, c);
    }

    const int g  = lane >> 2;
    const int tg = lane & 3;
    #pragma unroll
    for (int nf = 0; nf < 4; nf++) {
        const int col = bc + wn * 32 + nf * 8 + tg * 2;
        const float2 bb = *(const float2*)(b_o + col);
        #pragma unroll
        for (int mf = 0; mf < 2; mf++) {
            const int row0 = br + wm * 32 + mf * 16 + g;
            float2 v0 = make_float2(c[mf][nf][0] + bb.x, c[mf][nf][1] + bb.y);
            float2 v1 = make_float2(c[mf][nf][2] + bb.x, c[mf][nf][3] + bb.y);
            *(float2*)(out + (size_t)row0 * OUT_ + col)       = v0;
            *(float2*)(out + (size_t)(row0 + 8) * OUT_ + col) = v1;
        }
    }
}

// ==================================================================
// Launch
// ==================================================================
extern "C" void kernel_launch(void* const* d_in, const int* in_sizes, int n_in,
                              void* d_out, int out_size)
{
    const float* x    = (const float*)d_in[0];
    const float* mem  = (const float*)d_in[1];
    const float* W_ar = (const float*)d_in[2];
    const float* b_ar = (const float*)d_in[3];
    const float* W_pr = (const float*)d_in[4];
    const float* b_pr = (const float*)d_in[5];
    const float* W_f  = (const float*)d_in[6];
    const float* b_f  = (const float*)d_in[7];
    const float* W_r  = (const float*)d_in[8];
    const float* b_r  = (const float*)d_in[9];
    const float* W_o  = (const float*)d_in[10];
    const float* b_o  = (const float*)d_in[11];

    float* out     = (float*)d_out;
    float* new_mem = out + (size_t)B_ * OUT_;

    static cudaStream_t s1 = nullptr;
    static cudaEvent_t ev_root = nullptr, ev_side = nullptr;
    if (!s1) {
        cudaStreamCreateWithFlags(&s1, cudaStreamNonBlocking);
        cudaEventCreateWithFlags(&ev_root, cudaEventDisableTiming);
        cudaEventCreateWithFlags(&ev_side, cudaEventDisableTiming);
        cudaFuncSetAttribute(mem_kernel, cudaFuncAttributeMaxDynamicSharedMemorySize, MEM_SMEM);
        cudaFuncSetAttribute(proj_kernel, cudaFuncAttributeMaxDynamicSharedMemorySize, PROJ_SMEM);
        cudaFuncSetAttribute(out_gemm_mma, cudaFuncAttributeMaxDynamicSharedMemorySize, GEMM_SMEM);
    }

    // fork: conv_B on side stream
    cudaEventRecord(ev_root, 0);
    cudaStreamWaitEvent(s1, ev_root, 0);
    {
        dim3 g(KO / 32, OUT_ / 32);
        conv_B_kernel<<<g, 256, 0, s1>>>(W_o);
    }
    cudaEventRecord(ev_side, s1);

    // main chain
    pack_kernel<<<(P_XR + 255) / 256, 256>>>(W_ar, W_f, W_r, b_ar, b_f, b_r);
    {
        dim3 g(B_ / GROUP, 2);
        proj_kernel<<<g, PTH, PROJ_SMEM>>>(x);
    }
    mem_kernel<<<B_, MTH, MEM_SMEM>>>(mem, W_pr, b_pr, new_mem);

    // join, then GEMM
    cudaStreamWaitEvent(0, ev_side, 0);
    {
        dim3 g(OUT_ / CTA_N, B_ / CTA_M);
        out_gemm_mma<<<g, 256, GEMM_SMEM>>>(b_o, out);
    }
}

// round 17
// speedup vs baseline: 1.1020x; 1.0401x over previous
#include <cuda_runtime.h>
#include <cuda_bf16.h>
#include <math.h>
#include <cstdint>

// Problem constants
#define B_    512
#define NS    128
#define IN_   2048
#define MEM_  64
#define OUT_  2048
#define RCOLS 65
#define KO    2176          // IN_ + 2*MEM_
#define NPAD  132

// ------------------------------------------------------------------
// Scratch (device globals)
// ------------------------------------------------------------------
__device__ float g_q  [B_ * MEM_];      // bias-init by pack, atomicAdd by proj
__device__ float g_xf [B_];
__device__ float g_xr [B_ * RCOLS];
__device__ float g_W  [IN_ * NPAD];
__device__ __nv_bfloat16 g_Ahi[B_ * KO];
__device__ __nv_bfloat16 g_Alo[B_ * KO];
__device__ __nv_bfloat16 g_Bhi[OUT_ * KO];
__device__ __nv_bfloat16 g_Blo[OUT_ * KO];
__device__ __nv_bfloat16 g_WBhi[80 * 64];
__device__ __nv_bfloat16 g_WBlo[80 * 64];

// ------------------------------------------------------------------
// Helpers
// ------------------------------------------------------------------
__device__ __forceinline__ uint32_t smem_u32(const void* p) {
    uint32_t a;
    asm("{ .reg .u64 t; cvta.to.shared.u64 t, %1; cvt.u32.u64 %0, t; }"
        : "=r"(a) : "l"(p));
    return a;
}
__device__ __forceinline__ void cp16(uint32_t dst, const void* src) {
    asm volatile("cp.async.cg.shared.global [%0], [%1], 16;" :: "r"(dst), "l"(src));
}
#define CP_COMMIT()  asm volatile("cp.async.commit_group;" ::: "memory")
#define CP_WAIT(n)   asm volatile("cp.async.wait_group %0;" :: "n"(n) : "memory")

__device__ __forceinline__ void ldm_x4(uint32_t* r, uint32_t addr) {
    asm volatile("ldmatrix.sync.aligned.m8n8.x4.shared.b16 {%0,%1,%2,%3}, [%4];"
        : "=r"(r[0]), "=r"(r[1]), "=r"(r[2]), "=r"(r[3]) : "r"(addr));
}
__device__ __forceinline__ void mma16816(float* c, const uint32_t* a, const uint32_t* b) {
    asm volatile(
        "mma.sync.aligned.m16n8k16.row.col.f32.bf16.bf16.f32 "
        "{%0,%1,%2,%3}, {%4,%5,%6,%7}, {%8,%9}, {%0,%1,%2,%3};"
        : "+f"(c[0]), "+f"(c[1]), "+f"(c[2]), "+f"(c[3])
        : "r"(a[0]), "r"(a[1]), "r"(a[2]), "r"(a[3]), "r"(b[0]), "r"(b[1]));
}
__device__ __forceinline__ void split_bf16(float v, __nv_bfloat16& h, __nv_bfloat16& l) {
    h = __float2bfloat16(v);
    l = __float2bfloat16(v - __bfloat162float(h));
}

// ==================================================================
// Prep: pack weights + bias-init the projection accumulators.
// ==================================================================
#define P_W    (IN_ * NPAD)
#define P_WB   (P_W + 80 * 64)
#define P_Q    (P_WB + B_ * MEM_)
#define P_XF   (P_Q + B_)
#define P_XR   (P_XF + B_ * RCOLS)
__global__ __launch_bounds__(256) void pack_kernel(
    const float* __restrict__ W_ar, const float* __restrict__ W_f,
    const float* __restrict__ W_r,
    const float* __restrict__ b_ar, const float* __restrict__ b_f,
    const float* __restrict__ b_r)
{
    int idx = blockIdx.x * 256 + threadIdx.x;
    if (idx >= P_XR) return;
    if (idx < P_W) {
        int k = idx / NPAD, c = idx - k * NPAD;
        float v = 0.f;
        if (c < 64)       v = W_ar[(size_t)k * 64 + c];
        else if (c == 64) v = W_f[k];
        else if (c < 130) v = W_r[(size_t)k * RCOLS + (c - 65)];
        g_W[idx] = v;
    } else if (idx < P_WB) {
        int e = idx - P_W;
        int j = e >> 6, k = e & 63;
        float v = 0.f;
        if (j < 65)       v = W_r[(size_t)(IN_ + k) * RCOLS + j];
        else if (j == 65) v = W_f[IN_ + k];
        __nv_bfloat16 h, l;
        split_bf16(v, h, l);
        int dst = j * 64 + (((k >> 3) ^ (j & 7)) << 3) + (k & 7);
        g_WBhi[dst] = h;
        g_WBlo[dst] = l;
    } else if (idx < P_Q) {
        int e = idx - P_WB;
        g_q[e] = b_ar[e & 63];
    } else if (idx < P_XF) {
        g_xf[idx - P_Q] = b_f[0];
    } else {
        int e = idx - P_XF;
        g_xr[e] = b_r[e % RCOLS];
    }
}

// W_o [K=2176][N=2048] -> g_B* [N][K] bf16 hi/lo (tiled transpose)
__global__ __launch_bounds__(256) void conv_B_kernel(const float* __restrict__ W_o)
{
    __shared__ float t[32][33];
    const int k0 = blockIdx.x * 32;
    const int n0 = blockIdx.y * 32;
    const int tid = threadIdx.x;
    #pragma unroll
    for (int p = 0; p < 4; p++) {
        int r = (tid >> 5) + p * 8, c = tid & 31;
        t[r][c] = W_o[(size_t)(k0 + r) * OUT_ + n0 + c];
    }
    __syncthreads();
    #pragma unroll
    for (int p = 0; p < 2; p++) {
        int r = (tid >> 4) + p * 16;
        int cc = (tid & 15) * 2;
        float v0 = t[cc][r], v1 = t[cc + 1][r];
        __nv_bfloat16 h0, l0, h1, l1;
        split_bf16(v0, h0, l0);
        split_bf16(v1, h1, l1);
        __nv_bfloat162 hp; hp.x = h0; hp.y = h1;
        __nv_bfloat162 lp; lp.x = l0; lp.y = l1;
        *(__nv_bfloat162*)(g_Bhi + (size_t)(n0 + r) * KO + k0 + cc) = hp;
        *(__nv_bfloat162*)(g_Blo + (size_t)(n0 + r) * KO + k0 + cc) = lp;
    }
}

// ==================================================================
// Kernel A: projections, GROUP=8 x 2 k-halves, atomic combine.
// ==================================================================
#define GROUP 8
#define KHALF (IN_ / 2)
#define CW4   33
#define KQ2   16
#define PTH   (CW4 * KQ2)
#define KSLC  (KHALF / KQ2)

__global__ __launch_bounds__(PTH) void proj_kernel(const float* __restrict__ x)
{
    extern __shared__ float psm[];
    float* xs  = psm;
    float* red = psm + GROUP * KHALF;
    const int b0 = blockIdx.x * GROUP;
    const int kh = blockIdx.y;
    const int kofs = kh * KHALF;

    for (int i = threadIdx.x; i < GROUP * (KHALF / 4); i += PTH) {
        int g = i >> 8, k4 = i & 255;
        ((float4*)(xs + g * KHALF))[k4] =
            ((const float4*)(x + (size_t)(b0 + g) * IN_ + kofs))[k4];
    }
    __syncthreads();

    for (int i = threadIdx.x; i < GROUP * (KHALF / 8); i += PTH) {
        int g = i >> 7, c8 = (i & 127) << 3;
        __nv_bfloat16 h[8], l[8];
        #pragma unroll
        for (int j = 0; j < 8; j++) split_bf16(xs[g * KHALF + c8 + j], h[j], l[j]);
        *(uint4*)(g_Ahi + (size_t)(b0 + g) * KO + kofs + c8) = *(const uint4*)h;
        *(uint4*)(g_Alo + (size_t)(b0 + g) * KO + kofs + c8) = *(const uint4*)l;
    }

    const int t  = threadIdx.x;
    const int c4 = t % CW4;
    const int kq = t / CW4;
    const int kbase = kq * KSLC;

    float4 acc[GROUP];
    #pragma unroll
    for (int g = 0; g < GROUP; g++) acc[g] = make_float4(0.f, 0.f, 0.f, 0.f);

    const float4* wp = (const float4*)(g_W + (size_t)(kofs + kbase) * NPAD) + c4;
    #pragma unroll 8
    for (int k = 0; k < KSLC; k++) {
        const float4 w = wp[(size_t)k * (NPAD / 4)];
        const int kk = kbase + k;
        #pragma unroll
        for (int g = 0; g < GROUP; g++) {
            const float xv = xs[g * KHALF + kk];
            acc[g].x = fmaf(xv, w.x, acc[g].x);
            acc[g].y = fmaf(xv, w.y, acc[g].y);
            acc[g].z = fmaf(xv, w.z, acc[g].z);
            acc[g].w = fmaf(xv, w.w, acc[g].w);
        }
    }
    #pragma unroll
    for (int g = 0; g < GROUP; g++)
        *(float4*)&red[(g * KQ2 + kq) * NPAD + c4 * 4] = acc[g];
    __syncthreads();

    if (t < 130) {
        #pragma unroll
        for (int g = 0; g < GROUP; g++) {
            float s = 0.f;
            #pragma unroll
            for (int q = 0; q < KQ2; q++)
                s += red[(g * KQ2 + q) * NPAD + t];
            const int b = b0 + g;
            if (t < 64)       atomicAdd(&g_q[(size_t)b * MEM_ + t], s);
            else if (t == 64) atomicAdd(&g_xf[b], s);
            else              atomicAdd(&g_xr[(size_t)b * RCOLS + (t - 65)], s);
        }
    }
}
#define PROJ_SMEM ((GROUP * KHALF + GROUP * KQ2 * NPAD) * 4)

// ==================================================================
// Kernel B: memory-fused (R16 version, unchanged).
// ==================================================================
#define MTH   256
#define MSP   68
#define TAIL_OFF (8704 + 13312)
#define MEM_SMEM ((TAIL_OFF + 1024) * 4)

__device__ __forceinline__ void blockReduce2(
    float& va, float& vb, float* red16, int isSum)
{
    #pragma unroll
    for (int o = 16; o; o >>= 1) {
        float ua = __shfl_xor_sync(0xffffffffu, va, o);
        float ub = __shfl_xor_sync(0xffffffffu, vb, o);
        va = isSum ? (va + ua) : fmaxf(va, ua);
        vb = isSum ? (vb + ub) : fmaxf(vb, ub);
    }
    if ((threadIdx.x & 31) == 0) {
        red16[(threadIdx.x >> 5) * 2]     = va;
        red16[(threadIdx.x >> 5) * 2 + 1] = vb;
    }
    __syncthreads();
    float ra = red16[0], rb = red16[1];
    #pragma unroll
    for (int i = 1; i < 8; i++) {
        ra = isSum ? (ra + red16[2 * i])     : fmaxf(ra, red16[2 * i]);
        rb = isSum ? (rb + red16[2 * i + 1]) : fmaxf(rb, red16[2 * i + 1]);
    }
    __syncthreads();
    va = ra; vb = rb;
}

__global__ __launch_bounds__(MTH) void mem_kernel(
    const float* __restrict__ memory,
    const float* __restrict__ W_pr, const float* __restrict__ b_pr,
    float* __restrict__ new_memory)
{
    extern __shared__ float sm[];
    float* msf   = sm;
    char*  img   = (char*)(sm + 8704);
    float* qs    = sm + TAIL_OFF;
    float* wpr   = qs + 64;
    float* xrs   = wpr + 64;
    float* s1    = xrs + 68;
    float* s2    = s1 + 128;
    float* red16 = s2 + 128;
    float* pad   = red16 + 16;

    const int b    = blockIdx.x;
    const int t    = threadIdx.x;
    const int wid  = t >> 5;
    const int lane = t & 31;
    const float* memb = memory + (size_t)b * NS * MEM_;
    const float xfv = g_xf[b];

    if (t < 64) { qs[t] = g_q[(size_t)b * MEM_ + t]; wpr[t] = W_pr[t]; }
    if (t < 65) { xrs[t] = g_xr[(size_t)b * RCOLS + t]; }
    __syncthreads();

    {
        __nv_bfloat16* Ah = (__nv_bfloat16*)img;
        __nv_bfloat16* Al = (__nv_bfloat16*)(img + 16384);
        #pragma unroll
        for (int it = 0; it < 4; it++) {
            const int i8 = t + it * MTH;
            const int e = i8 * 8;
            const int n = e >> 6, m = e & 63, q = m >> 3;
            float4 v0 = *(const float4*)(memb + e);
            float4 v1 = *(const float4*)(memb + e + 4);
            *(float4*)&msf[n * MSP + m]     = v0;
            *(float4*)&msf[n * MSP + m + 4] = v1;
            const float vv[8] = {v0.x, v0.y, v0.z, v0.w, v1.x, v1.y, v1.z, v1.w};
            __nv_bfloat16 h[8], l[8];
            #pragma unroll
            for (int j = 0; j < 8; j++) split_bf16(vv[j], h[j], l[j]);
            const int idx = n * 64 + ((q ^ (n & 7)) << 3);
            *(uint4*)(Ah + idx) = *(const uint4*)h;
            *(uint4*)(Al + idx) = *(const uint4*)l;
            float pa = 0.f, pp = 0.f;
            #pragma unroll
            for (int j = 0; j < 8; j++) {
                pa = fmaf(vv[j], qs[m + j], pa);
                pp = fmaf(vv[j], wpr[m + j], pp);
            }
            pa += __shfl_xor_sync(0xffffffffu, pa, 1);
            pp += __shfl_xor_sync(0xffffffffu, pp, 1);
            pa += __shfl_xor_sync(0xffffffffu, pa, 2);
            pp += __shfl_xor_sync(0xffffffffu, pp, 2);
            pa += __shfl_xor_sync(0xffffffffu, pa, 4);
            pp += __shfl_xor_sync(0xffffffffu, pp, 4);
            if ((t & 7) == 0) { pad[n] = pa; pad[128 + n] = pp; }
        }
    }
    {
        const uint4* wbh = (const uint4*)g_WBhi;
        const uint4* wbl = (const uint4*)g_WBlo;
        uint4* Bh = (uint4*)(img + 32768);
        uint4* Bl = (uint4*)(img + 43008);
        for (int i = t; i < 1280; i += MTH) {
            if (i < 640) Bh[i] = wbh[i];
            else         Bl[i - 640] = wbl[i - 640];
        }
    }
    __syncthreads();

    const uint32_t Abase = smem_u32(img);
    const uint32_t Bbase = Abase + 32768;
    const int rr   = wid * 16;
    const int lrow = ((lane >> 3) & 1) * 8 + (lane & 7);
    const int lh   = (lane >> 4) & 1;

    float c[10][4];
    #pragma unroll
    for (int i = 0; i < 10; i++)
        #pragma unroll
        for (int q = 0; q < 4; q++) c[i][q] = 0.f;

    #pragma unroll
    for (int s = 0; s < 4; s++) {
        const int hb = s * 2 + lh;
        const int arow = rr + lrow;
        const uint32_t aoff = arow * 128 + ((hb ^ (arow & 7)) << 4);
        uint32_t ah[4], al[4];
        ldm_x4(ah, Abase + aoff);
        ldm_x4(al, Abase + 16384 + aoff);
        #pragma unroll
        for (int gp = 0; gp < 5; gp++) {
            const int jr = gp * 16 + lrow;
            const uint32_t boff = jr * 128 + ((hb ^ (jr & 7)) << 4);
            uint32_t r4[4], q4[4];
            ldm_x4(r4, Bbase + boff);
            ldm_x4(q4, Bbase + 10240 + boff);
            uint32_t bh0[2] = {r4[0], r4[2]}, bh1[2] = {r4[1], r4[3]};
            uint32_t bl0[2] = {q4[0], q4[2]}, bl1[2] = {q4[1], q4[3]};
            mma16816(c[gp * 2], ah, bh0);
            mma16816(c[gp * 2], ah, bl0);
            mma16816(c[gp * 2], al, bh0);
            mma16816(c[gp * 2 + 1], ah, bh1);
            mma16816(c[gp * 2 + 1], ah, bl1);
            mma16816(c[gp * 2 + 1], al, bh1);
        }
    }

    {
        const int g  = lane >> 2;
        const int tg = lane & 3;
        const int base = lane & ~3;
        const int row0 = rr + g;
        const int row1 = row0 + 8;

        const float gate0 = __shfl_sync(0xffffffffu, c[8][0], base) + xrs[64];
        const float fr0   = __shfl_sync(0xffffffffu, c[8][1], base);
        const float gate1 = __shfl_sync(0xffffffffu, c[8][2], base) + xrs[64];
        const float fr1   = __shfl_sync(0xffffffffu, c[8][3], base);
        const float f0 = 1.1f / (1.f + expf(-(fr0 + xfv)));
        const float f1 = 1.1f / (1.f + expf(-(fr1 + xfv)));

        float* nm = new_memory + (size_t)b * NS * MEM_;
        #pragma unroll
        for (int nf = 0; nf < 8; nf++) {
            const int col = nf * 8 + tg * 2;
            const float bx = xrs[col], by = xrs[col + 1];
            float2 o0, o1;
            o0.x = fmaf(msf[row0 * MSP + col],     f0, gate0 * (c[nf][0] + bx));
            o0.y = fmaf(msf[row0 * MSP + col + 1], f0, gate0 * (c[nf][1] + by));
            o1.x = fmaf(msf[row1 * MSP + col],     f1, gate1 * (c[nf][2] + bx));
            o1.y = fmaf(msf[row1 * MSP + col + 1], f1, gate1 * (c[nf][3] + by));
            *(float2*)(nm + row0 * MEM_ + col) = o0;
            *(float2*)(nm + row1 * MEM_ + col) = o1;
        }
    }

    float s1v = -1e30f, s2v = -1e30f;
    if (t < NS) {
        s1v = pad[t];
        s2v = pad[128 + t] + b_pr[0];
    }
    float m1 = s1v, m2 = s2v;
    blockReduce2(m1, m2, red16, 0);
    float e1 = (t < NS) ? expf(s1v - m1) : 0.f;
    float e2 = (t < NS) ? expf(s2v - m2) : 0.f;
    float u1 = e1, u2 = e2;
    blockReduce2(u1, u2, red16, 1);
    if (t < NS) { s1[t] = e1 / u1; s2[t] = e2 / u2; }
    __syncthreads();

    {
        const int col = t & 63;
        const int grp = t >> 6;
        float act = 0.f, pas = 0.f;
        #pragma unroll 4
        for (int n = grp * 32; n < grp * 32 + 32; n++) {
            float mv = msf[n * MSP + col];
            act = fmaf(s1[n], mv, act);
            pas = fmaf(s2[n], mv, pas);
        }
        pad[grp * 64 + col]       = act;
        pad[256 + grp * 64 + col] = pas;
    }
    __syncthreads();
    if (t < MEM_) {
        float act = pad[t] + pad[64 + t] + pad[128 + t] + pad[192 + t];
        float pas = pad[256 + t] + pad[320 + t] + pad[384 + t] + pad[448 + t];
        __nv_bfloat16 h, l;
        split_bf16(act, h, l);
        g_Ahi[(size_t)b * KO + IN_ + t] = h;
        g_Alo[(size_t)b * KO + IN_ + t] = l;
        split_bf16(pas, h, l);
        g_Ahi[(size_t)b * KO + IN_ + MEM_ + t] = h;
        g_Alo[(size_t)b * KO + IN_ + MEM_ + t] = l;
    }
}

// ==================================================================
// Kernel C: mma.sync bf16-split GEMM. KCHUNK=64, 3-stage ring,
// barrier-then-prefetch (34 barriers total). 128B rows, SW128.
// Stage: Ahi 8K | Alo 8K | Bhi 16K | Blo 16K = 48KB; 3 stages 144KB.
// ==================================================================
#define CTA_M   64
#define CTA_N   128
#define KCHUNK  64
#define NKC     34
#define A_TB    8192
#define B_TB    16384
#define STAGE_B (2 * A_TB + 2 * B_TB)     // 49152
#define GEMM_SMEM (3 * STAGE_B)           // 147456

__device__ __forceinline__ uint32_t swz128(int r, int h) {
    return (uint32_t)((h ^ (r & 7)) << 4);
}

__device__ __forceinline__ void gemm_prefetch(
    uint32_t smem, int tid, int br, int bc, int k0, int stage)
{
    const uint32_t sb = smem + stage * STAGE_B;
    // A: 2 tiles x 64 rows x 8 h = 1024 cp16
    #pragma unroll
    for (int q = 0; q < 4; q++) {
        int u = tid + q * 256;
        int tile = u >> 9, rm = u & 511;
        int r = rm >> 3, h = rm & 7;
        const __nv_bfloat16* src =
            (tile ? g_Alo : g_Ahi) + (size_t)(br + r) * KO + k0 + h * 8;
        cp16(sb + tile * A_TB + r * 128 + swz128(r, h), src);
    }
    // B: 2 tiles x 128 rows x 8 h = 2048 cp16
    #pragma unroll
    for (int q = 0; q < 8; q++) {
        int u = tid + q * 256;
        int tile = u >> 10, rm = u & 1023;
        int n = rm >> 3, h = rm & 7;
        const __nv_bfloat16* src =
            (tile ? g_Blo : g_Bhi) + (size_t)(bc + n) * KO + k0 + h * 8;
        cp16(sb + 2 * A_TB + tile * B_TB + n * 128 + swz128(n, h), src);
    }
    CP_COMMIT();
}

__device__ __forceinline__ void gemm_chunk(
    uint32_t sb, int wm, int wn, int lrow, int lh, float c[2][4][4])
{
    #pragma unroll
    for (int s = 0; s < 4; s++) {          // four k16 subs
        const int h = s * 2 + lh;
        uint32_t ah[2][4], al[2][4];
        #pragma unroll
        for (int f = 0; f < 2; f++) {
            int rr = wm * 32 + f * 16 + lrow;
            uint32_t aoff = rr * 128 + swz128(rr, h);
            ldm_x4(ah[f], sb + aoff);
            ldm_x4(al[f], sb + A_TB + aoff);
        }
        uint32_t bh[4][2], bl[4][2];
        #pragma unroll
        for (int jj = 0; jj < 2; jj++) {
            int nn = wn * 32 + jj * 16 + lrow;
            uint32_t boff = nn * 128 + swz128(nn, h);
            uint32_t r4[4];
            ldm_x4(r4, sb + 2 * A_TB + boff);
            bh[2 * jj][0] = r4[0]; bh[2 * jj + 1][0] = r4[1];
            bh[2 * jj][1] = r4[2]; bh[2 * jj + 1][1] = r4[3];
            ldm_x4(r4, sb + 2 * A_TB + B_TB + boff);
            bl[2 * jj][0] = r4[0]; bl[2 * jj + 1][0] = r4[1];
            bl[2 * jj][1] = r4[2]; bl[2 * jj + 1][1] = r4[3];
        }
        #pragma unroll
        for (int mf = 0; mf < 2; mf++)
            #pragma unroll
            for (int nf = 0; nf < 4; nf++) {
                mma16816(c[mf][nf], ah[mf], bh[nf]);
                mma16816(c[mf][nf], ah[mf], bl[nf]);
                mma16816(c[mf][nf], al[mf], bh[nf]);
            }
    }
}

__global__ __launch_bounds__(256) void out_gemm_mma(
    const float* __restrict__ b_o, float* __restrict__ out)
{
    extern __shared__ __align__(128) char gsm[];
    const int tid  = threadIdx.x;
    const int wid  = tid >> 5;
    const int lane = tid & 31;
    const int wm   = wid & 1;
    const int wn   = wid >> 1;
    const int br   = blockIdx.y * CTA_M;
    const int bc   = blockIdx.x * CTA_N;
    const uint32_t smem = smem_u32(gsm);

    float c[2][4][4];
    #pragma unroll
    for (int i = 0; i < 2; i++)
        #pragma unroll
        for (int j = 0; j < 4; j++)
            #pragma unroll
            for (int q = 0; q < 4; q++) c[i][j][q] = 0.f;

    const int lrow = ((lane >> 3) & 1) * 8 + (lane & 7);
    const int lh   = (lane >> 4) & 1;

    gemm_prefetch(smem, tid, br, bc, 0 * KCHUNK, 0);
    gemm_prefetch(smem, tid, br, bc, 1 * KCHUNK, 1);

    for (int kc = 0; kc < NKC; kc++) {
        __syncthreads();   // orders chunk kc-1 reads before stage reuse below
        if (kc + 2 < NKC) { gemm_prefetch(smem, tid, br, bc, (kc + 2) * KCHUNK, (kc + 2) % 3); CP_WAIT(2); }
        else if (kc + 1 < NKC) { CP_WAIT(1); }
        else { CP_WAIT(0); }
        gemm_chunk(smem + (kc % 3) * STAGE_B, wm, wn, lrow, lh, c);
    }

    const int g  = lane >> 2;
    const int tg = lane & 3;
    #pragma unroll
    for (int nf = 0; nf < 4; nf++) {
        const int col = bc + wn * 32 + nf * 8 + tg * 2;
        const float2 bb = *(const float2*)(b_o + col);
        #pragma unroll
        for (int mf = 0; mf < 2; mf++) {
            const int row0 = br + wm * 32 + mf * 16 + g;
            float2 v0 = make_float2(c[mf][nf][0] + bb.x, c[mf][nf][1] + bb.y);
            float2 v1 = make_float2(c[mf][nf][2] + bb.x, c[mf][nf][3] + bb.y);
            *(float2*)(out + (size_t)row0 * OUT_ + col)       = v0;
            *(float2*)(out + (size_t)(row0 + 8) * OUT_ + col) = v1;
        }
    }
}

// ==================================================================
// Launch
// ==================================================================
extern "C" void kernel_launch(void* const* d_in, const int* in_sizes, int n_in,
                              void* d_out, int out_size)
{
    const float* x    = (const float*)d_in[0];
    const float* mem  = (const float*)d_in[1];
    const float* W_ar = (const float*)d_in[2];
    const float* b_ar = (const float*)d_in[3];
    const float* W_pr = (const float*)d_in[4];
    const float* b_pr = (const float*)d_in[5];
    const float* W_f  = (const float*)d_in[6];
    const float* b_f  = (const float*)d_in[7];
    const float* W_r  = (const float*)d_in[8];
    const float* b_r  = (const float*)d_in[9];
    const float* W_o  = (const float*)d_in[10];
    const float* b_o  = (const float*)d_in[11];

    float* out     = (float*)d_out;
    float* new_mem = out + (size_t)B_ * OUT_;

    static cudaStream_t s1 = nullptr;
    static cudaEvent_t ev_root = nullptr, ev_side = nullptr;
    if (!s1) {
        cudaStreamCreateWithFlags(&s1, cudaStreamNonBlocking);
        cudaEventCreateWithFlags(&ev_root, cudaEventDisableTiming);
        cudaEventCreateWithFlags(&ev_side, cudaEventDisableTiming);
        cudaFuncSetAttribute(mem_kernel, cudaFuncAttributeMaxDynamicSharedMemorySize, MEM_SMEM);
        cudaFuncSetAttribute(proj_kernel, cudaFuncAttributeMaxDynamicSharedMemorySize, PROJ_SMEM);
        cudaFuncSetAttribute(out_gemm_mma, cudaFuncAttributeMaxDynamicSharedMemorySize, GEMM_SMEM);
    }

    // fork: conv_B on side stream
    cudaEventRecord(ev_root, 0);
    cudaStreamWaitEvent(s1, ev_root, 0);
    {
        dim3 g(KO / 32, OUT_ / 32);
        conv_B_kernel<<<g, 256, 0, s1>>>(W_o);
    }
    cudaEventRecord(ev_side, s1);

    // main chain
    pack_kernel<<<(P_XR + 255) / 256, 256>>>(W_ar, W_f, W_r, b_ar, b_f, b_r);
    {
        dim3 g(B_ / GROUP, 2);
        proj_kernel<<<g, PTH, PROJ_SMEM>>>(x);
    }
    mem_kernel<<<B_, MTH, MEM_SMEM>>>(mem, W_pr, b_pr, new_mem);

    // join, then GEMM
    cudaStreamWaitEvent(0, ev_side, 0);
    {
        dim3 g(OUT_ / CTA_N, B_ / CTA_M);
        out_gemm_mma<<<g, 256, GEMM_SMEM>>>(b_o, out);
    }
}